// round 14
// baseline (speedup 1.0000x reference)
#include <cuda_runtime.h>
#include <cstdint>

#define B_     8
#define N_     2048
#define FIN    256
#define FOUT   64
#define LOG2E  1.4426950408889634f
#define ONE_TF 0x3f800000u

// Scratch (device globals: allocation-free rule)
__device__ float    g_WhB[B_ * N_ * FOUT];  // [b][j>>3][o][j&7], tf32-pre-rounded
__device__ float    g_esrc[B_ * N_];        // log2-scaled src logits
__device__ float2   g_edEF[B_ * N_];        // per node: (exp2(d), exp2(0.2 d))

// ---------------------------------------------------------------------------
// helpers
// ---------------------------------------------------------------------------
__device__ __forceinline__ uint32_t smem_u32(const void* p) {
    uint32_t a;
    asm("{ .reg .u64 t; cvta.to.shared.u64 t, %1; cvt.u32.u64 %0, t; }" : "=r"(a) : "l"(p));
    return a;
}
__device__ __forceinline__ void cpa16(uint32_t dst, const void* src) {
    asm volatile("cp.async.cg.shared.global [%0], [%1], 16;" :: "r"(dst), "l"(src));
}
#define CP_COMMIT() asm volatile("cp.async.commit_group;" ::: "memory")
#define CP_WAIT1()  asm volatile("cp.async.wait_group 1;" ::: "memory")
#define BAR_GRP(id) asm volatile("bar.sync %0, 64;" :: "r"(id) : "memory")

__device__ __forceinline__ float ex2f(float x) {
    float r; asm("ex2.approx.f32 %0, %1;" : "=f"(r) : "f"(x)); return r;
}
__device__ __forceinline__ uint32_t tf32u(float x) {
    uint32_t r; asm("cvt.rn.tf32.f32 %0, %1;" : "=r"(r) : "f"(x)); return r;
}
__device__ __forceinline__ float tf32f(float x) {
    uint32_t r; asm("cvt.rn.tf32.f32 %0, %1;" : "=r"(r) : "f"(x));
    return __uint_as_float(r);
}
// D += A*B, m16n8k8 tf32 (base PTX ISA)
#define MMA_TF32(d, a0, a1, a2, a3, b0, b1)                                   \
    asm volatile("mma.sync.aligned.m16n8k8.row.col.f32.tf32.tf32.f32 "        \
                 "{%0,%1,%2,%3}, {%4,%5,%6,%7}, {%8,%9}, {%0,%1,%2,%3};"      \
                 : "+f"((d)[0]), "+f"((d)[1]), "+f"((d)[2]), "+f"((d)[3])     \
                 : "r"(a0), "r"(a1), "r"(a2), "r"(a3), "r"(b0), "r"(b1))

// packed fp32x2 FMA (prep kernel)
#define FMA2(d, a, b) asm("fma.rn.f32x2 %0, %1, %2, %0;" : "+l"(d) : "l"(a), "l"(b))
__device__ __forceinline__ float pair_sum(unsigned long long v) {
    float lo, hi;
    asm("mov.b64 {%0, %1}, %2;" : "=f"(lo), "=f"(hi) : "l"(v));
    return lo + hi;
}
__device__ __forceinline__ unsigned long long pack2(float lo, float hi) {
    unsigned long long r;
    asm("mov.b64 %0, {%1, %2};" : "=l"(r) : "f"(lo), "f"(hi));
    return r;
}

// ---------------------------------------------------------------------------
// Kernel PREP: Wh = h @ W via FFMA2. 256 blocks x 256 threads, 64 rows/block,
// 2 blocks/SM. ALL of W staged pair-packed ONCE (64KB); h double-buffered
// cp.async. NEW: epilogue transposes results through smem (reusing h buffers)
// so g_WhB stores are fully-coalesced float4 (old path: 1 value per 32B
// sector -> ~8x write amplification + 1M wavefronts).
// ---------------------------------------------------------------------------
#define HB_OFF 65536      // byte offset of h buffers (2 x 9216)

__global__ __launch_bounds__(256, 2) void gat_prep(const float* __restrict__ h,
                                                   const float* __restrict__ W,
                                                   const float* __restrict__ a) {
    extern __shared__ char sA[];
    unsigned long long* Wp = (unsigned long long*)sA;   // 8192 ull = 64KB
    float* hb = (float*)(sA + HB_OFF);                  // 2 x (64 rows x 36)
    uint32_t hbase = smem_u32(sA) + HB_OFF;

    int t = threadIdx.x;
    int rg = t >> 4, op = t & 15;
    int row0 = blockIdx.x * 64;

    int r0 = t >> 3, f0 = t & 7;
    int r1 = (t + 256) >> 3, f1 = t & 7;
    const float* hsrc = h + (size_t)row0 * FIN;

    {   // chunks 0, 1
        cpa16(hbase + r0 * 144 + f0 * 16, hsrc + (size_t)r0 * FIN + f0 * 4);
        cpa16(hbase + r1 * 144 + f1 * 16, hsrc + (size_t)r1 * FIN + f1 * 4);
        CP_COMMIT();
        cpa16(hbase + 9216 + r0 * 144 + f0 * 16, hsrc + (size_t)r0 * FIN + 32 + f0 * 4);
        cpa16(hbase + 9216 + r1 * 144 + f1 * 16, hsrc + (size_t)r1 * FIN + 32 + f1 * 4);
        CP_COMMIT();
    }

    // stage ALL W pairs: Wp[kp*64+o] = (W[2kp][o], W[2kp+1][o])
#pragma unroll 4
    for (int idx = t; idx < 8192; idx += 256) {
        int kp = idx >> 6, o = idx & 63;
        Wp[idx] = pack2(__ldg(W + (2 * kp) * FOUT + o), __ldg(W + (2 * kp + 1) * FOUT + o));
    }

    unsigned long long acc[4][4];
#pragma unroll
    for (int q = 0; q < 4; q++)
#pragma unroll
        for (int s = 0; s < 4; s++) acc[q][s] = 0ull;

    for (int c = 0; c < 8; c++) {
        CP_WAIT1();
        __syncthreads();
        const float* hc = hb + (c & 1) * 2304;
#pragma unroll
        for (int kpl = 0; kpl < 16; kpl++) {
            const ulonglong2* wrow = (const ulonglong2*)(Wp + (c * 16 + kpl) * 64);
            ulonglong2 wa = wrow[op];
            ulonglong2 wb = wrow[op + 16];
#pragma unroll
            for (int q = 0; q < 4; q++) {
                unsigned long long hv =
                    *(const unsigned long long*)(hc + (rg * 4 + q) * 36 + 2 * kpl);
                FMA2(acc[q][0], hv, wa.x);
                FMA2(acc[q][1], hv, wa.y);
                FMA2(acc[q][2], hv, wb.x);
                FMA2(acc[q][3], hv, wb.y);
            }
        }
        __syncthreads();
        if (c + 2 < 8) {
            uint32_t dst = hbase + (c & 1) * 9216;
            const float* src = hsrc + (c + 2) * 32;
            cpa16(dst + r0 * 144 + f0 * 16, src + (size_t)r0 * FIN + f0 * 4);
            cpa16(dst + r1 * 144 + f1 * 16, src + (size_t)r1 * FIN + f1 * 4);
        }
        CP_COMMIT();
    }

    int ov[4] = {2 * op, 2 * op + 1, 2 * op + 32, 2 * op + 33};
    float a1v[4], a2v[4];
#pragma unroll
    for (int s = 0; s < 4; s++) { a1v[s] = a[ov[s]]; a2v[s] = a[FOUT + ov[s]]; }

    // epilogue: e_src/e_dst (exact fp32) + transpose vals into smem
    float* sT = (float*)(sA + HB_OFF);   // 64 x 66 floats, reuses h buffers
#pragma unroll
    for (int q = 0; q < 4; q++) {
        int r = rg * 4 + q;
        int grow = row0 + r;
        float vals[4], v1 = 0.f, v2 = 0.f;
#pragma unroll
        for (int s = 0; s < 4; s++) {
            vals[s] = pair_sum(acc[q][s]);
            v1 += vals[s] * a1v[s];
            v2 += vals[s] * a2v[s];
        }
        *(float2*)(sT + r * 66 + 2 * op)      = make_float2(vals[0], vals[1]);
        *(float2*)(sT + r * 66 + 2 * op + 32) = make_float2(vals[2], vals[3]);
#pragma unroll
        for (int off = 1; off < 16; off <<= 1) {
            v1 += __shfl_xor_sync(0xffffffffu, v1, off);
            v2 += __shfl_xor_sync(0xffffffffu, v2, off);
        }
        if (op == 0) {
            float s = v1 * LOG2E, d = v2 * LOG2E;
            g_esrc[grow] = s;
            g_edEF[grow] = make_float2(ex2f(d), ex2f(0.2f * d));
        }
    }
    __syncthreads();

    // coalesced g_WhB stores: block region = 4096 floats contiguous (tf32)
    float* gdst = g_WhB + (size_t)blockIdx.x * 4096;
#pragma unroll
    for (int k = 0; k < 4; k++) {
        int idx = k * 256 + t;             // float4 index 0..1023
        int oct = idx >> 7;
        int f4i = idx & 127;
        int o   = f4i >> 1;
        int jh  = (f4i & 1) * 4;
        int rb  = oct * 8 + jh;            // rows rb..rb+3
        float4 v;
        v.x = tf32f(sT[(rb + 0) * 66 + o]);
        v.y = tf32f(sT[(rb + 1) * 66 + o]);
        v.z = tf32f(sT[(rb + 2) * 66 + o]);
        v.w = tf32f(sT[(rb + 3) * 66 + o]);
        *(float4*)(gdst + idx * 4) = v;
    }
}

// ---------------------------------------------------------------------------
// Kernel B: streaming attention -> mma.sync tf32 P @ Wh.
// Grid (32,8)=256 blocks x 256 threads, 2 blocks/SM.
// 4 GROUPS of 2 warps: g = w>>1 (j-quarter, 512 j), rh = w&1 (rows rh*32..
// +31 = TWO m16 fragments -> each B LDS.64 feeds 2 MMAs, halving B traffic).
// 32 chunks of 16 j per quarter; slice = Wh 4KB + raw adj 64x16 int
// (row stride 80B, 5KB) + EF 128B, triple-buffered cp.async, group-scoped
// named barrier (64 thr). adj touched exactly once chip-wide.
// p = adj>0 ? max(Ei*Ej, Fi*Fj) : 0 (== exp2(leaky)), tf32.
// Rowsum via ones-B MMA (same tf32 p -> exact normalization).
// ---------------------------------------------------------------------------
#define ADJ_OFF  4096
#define EF_OFF   9216
#define SLICE_SZ 9344                      // 4096 Wh + 5120 adj + 128 EF
#define SM_TOTB  (4 * 3 * SLICE_SZ)        // 112128

__device__ __forceinline__ void pf_slice(uint32_t dst, const char* whsrc,
                                         const char* adjsrc, const float2* efsrc,
                                         int g, int cc, int lt) {
    // Wh: 4KB contiguous (2 j-octet groups of 2048B)
    const char* wsrc = whsrc + (size_t)(g * 64 + cc * 2) * 2048;
#pragma unroll
    for (int i = 0; i < 4; i++)
        cpa16(dst + (lt + 64 * i) * 16, wsrc + (size_t)(lt + 64 * i) * 16);
    // adj: 64 rows x 64B (16 ints), row stride 8KB in gmem, 80B in smem
#pragma unroll
    for (int i = 0; i < 4; i++) {
        int idx = i * 64 + lt;             // 256 x 16B
        int r = idx >> 2, u = idx & 3;
        cpa16(dst + ADJ_OFF + r * 80 + u * 16,
              adjsrc + ((size_t)r << 13) + (size_t)(g * 512 + cc * 16) * 4 + u * 16);
    }
    if (lt < 8)
        cpa16(dst + EF_OFF + lt * 16,
              (const char*)efsrc + (size_t)(g * 512 + cc * 16) * 8 + lt * 16);
}

__global__ __launch_bounds__(256, 2) void gat_attn(const int* __restrict__ adj,
                                                   float* __restrict__ out) {
    extern __shared__ char sm[];
    uint32_t smb = smem_u32(sm);

    int t = threadIdx.x;
    int w = t >> 5, lane = t & 31;
    int q = lane >> 2, c = lane & 3;
    int b = blockIdx.y;
    int i0 = blockIdx.x * 64;
    int rowbase = b * N_;
    int g = w >> 1, rh = w & 1;
    int lr0 = rh * 32 + q;                 // rows lr0, +8, +16, +24
    int lt = t & 63;
    uint32_t slice0 = smb + g * 3 * SLICE_SZ;

    const char*   whsrc  = (const char*)(g_WhB + (size_t)b * N_ * FOUT);
    const char*   adjsrc = (const char*)(adj + ((size_t)(rowbase + i0) << 11));
    const float2* efsrc  = g_edEF + rowbase;

    float Ei[4], Fi[4];
#pragma unroll
    for (int m = 0; m < 4; m++) {
        float si = g_esrc[rowbase + i0 + lr0 + 8 * m];
        Ei[m] = ex2f(si);
        Fi[m] = ex2f(0.2f * si);
    }

    pf_slice(slice0, whsrc, adjsrc, efsrc, g, 0, lt);            CP_COMMIT();
    pf_slice(slice0 + SLICE_SZ, whsrc, adjsrc, efsrc, g, 1, lt); CP_COMMIT();

    float acc[2][8][4];
#pragma unroll
    for (int f = 0; f < 2; f++)
#pragma unroll
        for (int nt = 0; nt < 8; nt++)
#pragma unroll
            for (int s = 0; s < 4; s++) acc[f][nt][s] = 0.f;
    float acc_rs[2][4];
#pragma unroll
    for (int f = 0; f < 2; f++)
#pragma unroll
        for (int s = 0; s < 4; s++) acc_rs[f][s] = 0.f;

#pragma unroll 1
    for (int cc = 0; cc < 32; cc++) {
        CP_WAIT1();
        BAR_GRP(g + 1);
        if (cc + 2 < 32)
            pf_slice(slice0 + ((cc + 2) % 3) * SLICE_SZ, whsrc, adjsrc, efsrc,
                     g, cc + 2, lt);
        CP_COMMIT();

        const char*  Sc = sm + (size_t)(g * 3 + (cc % 3)) * SLICE_SZ;
        const float* Bc = (const float*)Sc;
        const int*   Ac = (const int*)(Sc + ADJ_OFF);
        const float* Ec = (const float*)(Sc + EF_OFF);

#pragma unroll
        for (int ks = 0; ks < 2; ks++) {
            int2 A[4];
#pragma unroll
            for (int m = 0; m < 4; m++)
                A[m] = *(const int2*)(Ac + (lr0 + 8 * m) * 20 + ks * 8 + 2 * c);
            float4 ef = *(const float4*)(Ec + (ks * 8 + 2 * c) * 2);
            uint32_t p[4][2];
#pragma unroll
            for (int m = 0; m < 4; m++) {
                p[m][0] = A[m].x > 0 ? tf32u(fmaxf(Ei[m] * ef.x, Fi[m] * ef.y)) : 0u;
                p[m][1] = A[m].y > 0 ? tf32u(fmaxf(Ei[m] * ef.z, Fi[m] * ef.w)) : 0u;
            }
#pragma unroll
            for (int nt = 0; nt < 8; nt++) {
                float2 wv = *(const float2*)(Bc + ks * 512 + (nt * 8 + q) * 8 + 2 * c);
                uint32_t b0 = __float_as_uint(wv.x), b1 = __float_as_uint(wv.y);
                MMA_TF32(acc[0][nt], p[0][0], p[1][0], p[0][1], p[1][1], b0, b1);
                MMA_TF32(acc[1][nt], p[2][0], p[3][0], p[2][1], p[3][1], b0, b1);
            }
            MMA_TF32(acc_rs[0], p[0][0], p[1][0], p[0][1], p[1][1], ONE_TF, ONE_TF);
            MMA_TF32(acc_rs[1], p[2][0], p[3][0], p[2][1], p[3][1], ONE_TF, ONE_TF);
        }
    }

    // combine the 4 j-quarters via smem (reuses staging)
    float* dsm = (float*)sm;                 // [3][64][66]
    float* rsm = (float*)(sm + 50688);       // [3][64]
    __syncthreads();
    if (g != 0) {
        float* dst = dsm + (g - 1) * 4224;
#pragma unroll
        for (int f = 0; f < 2; f++) {
            int r0_ = rh * 32 + 16 * f + q;
#pragma unroll
            for (int nt = 0; nt < 8; nt++) {
                *(float2*)(dst + r0_ * 66 + nt * 8 + 2 * c) =
                    make_float2(acc[f][nt][0], acc[f][nt][1]);
                *(float2*)(dst + (r0_ + 8) * 66 + nt * 8 + 2 * c) =
                    make_float2(acc[f][nt][2], acc[f][nt][3]);
            }
            if (c == 0) {
                rsm[(g - 1) * 64 + r0_]     = acc_rs[f][0];
                rsm[(g - 1) * 64 + r0_ + 8] = acc_rs[f][2];
            }
        }
    }
    __syncthreads();
    if (g == 0) {
#pragma unroll
        for (int f = 0; f < 2; f++) {
            int r0_ = rh * 32 + 16 * f + q;
            float i0v = 1.0f / (acc_rs[f][0] + rsm[r0_] + rsm[64 + r0_] + rsm[128 + r0_]);
            float i8v = 1.0f / (acc_rs[f][2] + rsm[r0_ + 8] + rsm[64 + r0_ + 8]
                                + rsm[128 + r0_ + 8]);
            float* o0 = out + (size_t)(rowbase + i0 + r0_) * FOUT;
            float* o8 = out + (size_t)(rowbase + i0 + r0_ + 8) * FOUT;
#pragma unroll
            for (int nt = 0; nt < 8; nt++) {
                int col = nt * 8 + 2 * c;
                float s0x = acc[f][nt][0], s0y = acc[f][nt][1];
                float s1x = acc[f][nt][2], s1y = acc[f][nt][3];
#pragma unroll
                for (int pp = 0; pp < 3; pp++) {
                    const float* dp = dsm + pp * 4224;
                    float2 d0 = *(const float2*)(dp + r0_ * 66 + col);
                    float2 d1 = *(const float2*)(dp + (r0_ + 8) * 66 + col);
                    s0x += d0.x; s0y += d0.y;
                    s1x += d1.x; s1y += d1.y;
                }
                float y;
                float2 v0, v8;
                y = s0x * i0v; v0.x = y > 0.f ? y : expm1f(y);
                y = s0y * i0v; v0.y = y > 0.f ? y : expm1f(y);
                y = s1x * i8v; v8.x = y > 0.f ? y : expm1f(y);
                y = s1y * i8v; v8.y = y > 0.f ? y : expm1f(y);
                *(float2*)(o0 + col) = v0;
                *(float2*)(o8 + col) = v8;
            }
        }
    }
}

// ---------------------------------------------------------------------------
extern "C" void kernel_launch(void* const* d_in, const int* in_sizes, int n_in,
                              void* d_out, int out_size) {
    const float* h   = (const float*)d_in[0];
    const int*   adj = (const int*)d_in[1];
    const float* W   = (const float*)d_in[2];
    const float* a   = (const float*)d_in[3];
    float*       out = (float*)d_out;

    const int smemA = HB_OFF + 2 * 9216;   // 83968
    cudaFuncSetAttribute(gat_prep, cudaFuncAttributeMaxDynamicSharedMemorySize, smemA);
    cudaFuncSetAttribute(gat_attn, cudaFuncAttributeMaxDynamicSharedMemorySize, SM_TOTB);

    gat_prep<<<(B_ * N_) / 64, 256, smemA>>>(h, W, a);

    dim3 gridB(N_ / 64, B_);   // (32, 8) = 256 blocks
    gat_attn<<<gridB, 256, SM_TOTB>>>(adj, out);
}

// round 15
// speedup vs baseline: 1.1828x; 1.1828x over previous
#include <cuda_runtime.h>
#include <cstdint>

#define B_     8
#define N_     2048
#define FIN    256
#define FOUT   64
#define LOG2E  1.4426950408889634f
#define ONE_H2 0x3c003c00u   // fp16x2 {1.0, 1.0}

// Scratch (device globals: allocation-free rule)
__device__ uint2  g_WhH[B_ * N_ * FOUT / 4];  // fp16 Wh, quad layout [b][j>>4][o][c]{j2c,j2c+1,j2c+8,j2c+9}
__device__ float  g_esrc[B_ * N_];            // log2-scaled src logits
__device__ float2 g_edEF[B_ * N_];            // per node: (exp2(d), exp2(0.2 d))

// ---------------------------------------------------------------------------
// helpers
// ---------------------------------------------------------------------------
__device__ __forceinline__ uint32_t smem_u32(const void* p) {
    uint32_t a;
    asm("{ .reg .u64 t; cvta.to.shared.u64 t, %1; cvt.u32.u64 %0, t; }" : "=r"(a) : "l"(p));
    return a;
}
__device__ __forceinline__ void cpa16(uint32_t dst, const void* src) {
    asm volatile("cp.async.cg.shared.global [%0], [%1], 16;" :: "r"(dst), "l"(src));
}
#define CP_COMMIT() asm volatile("cp.async.commit_group;" ::: "memory")
#define CP_WAIT1()  asm volatile("cp.async.wait_group 1;" ::: "memory")
#define BAR_PAIR(id) asm volatile("bar.sync %0, 128;" :: "r"(id) : "memory")

__device__ __forceinline__ float ex2f(float x) {
    float r; asm("ex2.approx.f32 %0, %1;" : "=f"(r) : "f"(x)); return r;
}
// pack two f32 -> fp16x2 (lo = second operand), satfinite clamps overflow
__device__ __forceinline__ uint32_t f16x2(float hi, float lo) {
    uint32_t r;
    asm("cvt.rn.satfinite.f16x2.f32 %0, %1, %2;" : "=r"(r) : "f"(hi), "f"(lo));
    return r;
}
// D += A*B, m16n8k16 fp16 -> f32 accum (base PTX ISA)
#define MMA_F16(d, a0, a1, a2, a3, b0, b1)                                    \
    asm volatile("mma.sync.aligned.m16n8k16.row.col.f32.f16.f16.f32 "         \
                 "{%0,%1,%2,%3}, {%4,%5,%6,%7}, {%8,%9}, {%0,%1,%2,%3};"      \
                 : "+f"((d)[0]), "+f"((d)[1]), "+f"((d)[2]), "+f"((d)[3])     \
                 : "r"(a0), "r"(a1), "r"(a2), "r"(a3), "r"(b0), "r"(b1))

// packed fp32x2 FMA (prep kernel)
#define FMA2(d, a, b) asm("fma.rn.f32x2 %0, %1, %2, %0;" : "+l"(d) : "l"(a), "l"(b))
__device__ __forceinline__ float pair_sum(unsigned long long v) {
    float lo, hi;
    asm("mov.b64 {%0, %1}, %2;" : "=f"(lo), "=f"(hi) : "l"(v));
    return lo + hi;
}
__device__ __forceinline__ unsigned long long pack2(float lo, float hi) {
    unsigned long long r;
    asm("mov.b64 %0, {%1, %2};" : "=l"(r) : "f"(lo), "f"(hi));
    return r;
}

// ---------------------------------------------------------------------------
// Kernel PREP: Wh = h @ W via FFMA2 (fp32). 256 blocks x 256 threads,
// 64 rows/block, 2 blocks/SM. ALL of W staged pair-packed ONCE (64KB);
// h double-buffered cp.async. Epilogue: transpose through smem, pack fp16
// quads {j2c,j2c+1,j2c+8,j2c+9} per (o,c) -> coalesced uint2 stores (8KB/blk).
// Also stores g_esrc (log2-scaled) and g_edEF = (exp2(d), exp2(0.2d)).
// ---------------------------------------------------------------------------
#define HB_OFF 65536      // byte offset of h buffers (2 x 9216)

__global__ __launch_bounds__(256, 2) void gat_prep(const float* __restrict__ h,
                                                   const float* __restrict__ W,
                                                   const float* __restrict__ a) {
    extern __shared__ char sA[];
    unsigned long long* Wp = (unsigned long long*)sA;   // 8192 ull = 64KB
    float* hb = (float*)(sA + HB_OFF);                  // 2 x (64 rows x 36)
    uint32_t hbase = smem_u32(sA) + HB_OFF;

    int t = threadIdx.x;
    int rg = t >> 4, op = t & 15;
    int row0 = blockIdx.x * 64;

    int r0 = t >> 3, f0 = t & 7;
    int r1 = (t + 256) >> 3, f1 = t & 7;
    const float* hsrc = h + (size_t)row0 * FIN;

    {   // chunks 0, 1
        cpa16(hbase + r0 * 144 + f0 * 16, hsrc + (size_t)r0 * FIN + f0 * 4);
        cpa16(hbase + r1 * 144 + f1 * 16, hsrc + (size_t)r1 * FIN + f1 * 4);
        CP_COMMIT();
        cpa16(hbase + 9216 + r0 * 144 + f0 * 16, hsrc + (size_t)r0 * FIN + 32 + f0 * 4);
        cpa16(hbase + 9216 + r1 * 144 + f1 * 16, hsrc + (size_t)r1 * FIN + 32 + f1 * 4);
        CP_COMMIT();
    }

    // stage ALL W pairs: Wp[kp*64+o] = (W[2kp][o], W[2kp+1][o])
#pragma unroll 4
    for (int idx = t; idx < 8192; idx += 256) {
        int kp = idx >> 6, o = idx & 63;
        Wp[idx] = pack2(__ldg(W + (2 * kp) * FOUT + o), __ldg(W + (2 * kp + 1) * FOUT + o));
    }

    unsigned long long acc[4][4];
#pragma unroll
    for (int q = 0; q < 4; q++)
#pragma unroll
        for (int s = 0; s < 4; s++) acc[q][s] = 0ull;

    for (int c = 0; c < 8; c++) {
        CP_WAIT1();
        __syncthreads();
        const float* hc = hb + (c & 1) * 2304;
#pragma unroll
        for (int kpl = 0; kpl < 16; kpl++) {
            const ulonglong2* wrow = (const ulonglong2*)(Wp + (c * 16 + kpl) * 64);
            ulonglong2 wa = wrow[op];
            ulonglong2 wb = wrow[op + 16];
#pragma unroll
            for (int q = 0; q < 4; q++) {
                unsigned long long hv =
                    *(const unsigned long long*)(hc + (rg * 4 + q) * 36 + 2 * kpl);
                FMA2(acc[q][0], hv, wa.x);
                FMA2(acc[q][1], hv, wa.y);
                FMA2(acc[q][2], hv, wb.x);
                FMA2(acc[q][3], hv, wb.y);
            }
        }
        __syncthreads();
        if (c + 2 < 8) {
            uint32_t dst = hbase + (c & 1) * 9216;
            const float* src = hsrc + (c + 2) * 32;
            cpa16(dst + r0 * 144 + f0 * 16, src + (size_t)r0 * FIN + f0 * 4);
            cpa16(dst + r1 * 144 + f1 * 16, src + (size_t)r1 * FIN + f1 * 4);
        }
        CP_COMMIT();
    }

    int ov[4] = {2 * op, 2 * op + 1, 2 * op + 32, 2 * op + 33};
    float a1v[4], a2v[4];
#pragma unroll
    for (int s = 0; s < 4; s++) { a1v[s] = a[ov[s]]; a2v[s] = a[FOUT + ov[s]]; }

    // epilogue: e_src/e_dst (exact fp32) + transpose vals into smem
    float* sT = (float*)(sA + HB_OFF);   // 64 x 66 floats, reuses h buffers
#pragma unroll
    for (int q = 0; q < 4; q++) {
        int r = rg * 4 + q;
        int grow = row0 + r;
        float vals[4], v1 = 0.f, v2 = 0.f;
#pragma unroll
        for (int s = 0; s < 4; s++) {
            vals[s] = pair_sum(acc[q][s]);
            v1 += vals[s] * a1v[s];
            v2 += vals[s] * a2v[s];
        }
        *(float2*)(sT + r * 66 + 2 * op)      = make_float2(vals[0], vals[1]);
        *(float2*)(sT + r * 66 + 2 * op + 32) = make_float2(vals[2], vals[3]);
#pragma unroll
        for (int off = 1; off < 16; off <<= 1) {
            v1 += __shfl_xor_sync(0xffffffffu, v1, off);
            v2 += __shfl_xor_sync(0xffffffffu, v2, off);
        }
        if (op == 0) {
            float s = v1 * LOG2E, d = v2 * LOG2E;
            g_esrc[grow] = s;
            g_edEF[grow] = make_float2(ex2f(d), ex2f(0.2f * d));
        }
    }
    __syncthreads();

    // fp16 quad stores: block region = 1024 uint2 contiguous, coalesced
    uint2* gdst = g_WhH + (size_t)blockIdx.x * 1024;
    int o = t >> 2, cq = t & 3;
#pragma unroll
    for (int k = 0; k < 4; k++) {
        int jl = k * 16 + 2 * cq;
        float v00 = sT[jl * 66 + o],       v01 = sT[(jl + 1) * 66 + o];
        float v10 = sT[(jl + 8) * 66 + o], v11 = sT[(jl + 9) * 66 + o];
        uint2 pk;
        pk.x = f16x2(v01, v00);   // b0: j 2c (lo), 2c+1 (hi)
        pk.y = f16x2(v11, v10);   // b1: j 2c+8, 2c+9
        gdst[k * 256 + t] = pk;
    }
}

// ---------------------------------------------------------------------------
// Kernel B: streaming attention -> mma.sync fp16 m16n8k16 P @ Wh (f32 accum).
// Grid (32,8)=256 blocks x 256 threads, 2 blocks/SM.
// 2 PAIRS of 4 warps (r13 structure): jq = w>>2 (j-half), wp = w&3 (one m16
// fragment, rows wp*16+q, +8). 32 chunks of 32 j per half; slice = fp16 Wh
// quads 4KB + raw adj 64x32 int (stride 36, 9KB) + EF 256B, triple-buffered
// cp.async, pair-scoped named barrier. adj touched once chip-wide.
// p = adj>0 ? 2^-2 * max(Ei*Ej, Fi*Fj) : 0 (== exp2(leaky)*2^-2; the scale
// cancels exactly in normalization; keeps fp16 range safe). fp16 mantissa ==
// tf32 mantissa (10b) -> identical accuracy, half the MMAs/B-LDS/cvts.
// Rowsum via ones-B MMA (same fp16 p -> exact normalization).
// ---------------------------------------------------------------------------
#define ADJ_OFF  4096
#define EF_OFF   13312
#define SLICE_SZ 13568                     // 4096 Wh + 9216 adj + 256 EF
#define SM_TOTB  (2 * 3 * SLICE_SZ)        // 81408

__device__ __forceinline__ void pf_slice(uint32_t dst, const char* whsrc,
                                         const char* adjsrc, const float2* efsrc,
                                         int jq, int cc, int lt) {
    // Wh fp16 quads: 4KB contiguous (2 j-blocks of 2048B)
    const char* wsrc = whsrc + (size_t)(jq * 64 + cc * 2) * 2048;
#pragma unroll
    for (int i = 0; i < 2; i++)
        cpa16(dst + (lt + 128 * i) * 16, wsrc + (size_t)(lt + 128 * i) * 16);
    // adj: 64 rows x 128B, row stride 8KB in gmem, 144B in smem
#pragma unroll
    for (int i = 0; i < 4; i++) {
        int idx = i * 128 + lt;            // 512 x 16B
        int r = idx >> 3, u = idx & 7;
        cpa16(dst + ADJ_OFF + r * 144 + u * 16,
              adjsrc + ((size_t)r << 13) + (size_t)(jq * 4096 + cc * 128) + u * 16);
    }
    if (lt < 16)
        cpa16(dst + EF_OFF + lt * 16,
              (const char*)(efsrc + (size_t)jq * 1024 + cc * 32) + lt * 16);
}

__global__ __launch_bounds__(256, 2) void gat_attn(const int* __restrict__ adj,
                                                   float* __restrict__ out) {
    extern __shared__ char sm[];
    uint32_t smb = smem_u32(sm);

    int t = threadIdx.x;
    int w = t >> 5, lane = t & 31;
    int q = lane >> 2, c = lane & 3;
    int b = blockIdx.y;
    int i0 = blockIdx.x * 64;
    int rowbase = b * N_;
    int jq = w >> 2, wp = w & 3;
    int lr0 = wp * 16 + q;
    int lt = t & 127;
    uint32_t slice0 = smb + jq * 3 * SLICE_SZ;

    const char*   whsrc  = (const char*)g_WhH + (size_t)b * (N_ * FOUT * 2);
    const char*   adjsrc = (const char*)(adj + ((size_t)(rowbase + i0) << 11));
    const float2* efsrc  = g_edEF + rowbase;

    float si0 = g_esrc[rowbase + i0 + lr0];
    float si8 = g_esrc[rowbase + i0 + lr0 + 8];
    float Ei0 = ex2f(si0 - 2.0f), Fi0 = ex2f(0.2f * si0 - 2.0f);
    float Ei8 = ex2f(si8 - 2.0f), Fi8 = ex2f(0.2f * si8 - 2.0f);

    pf_slice(slice0, whsrc, adjsrc, efsrc, jq, 0, lt);            CP_COMMIT();
    pf_slice(slice0 + SLICE_SZ, whsrc, adjsrc, efsrc, jq, 1, lt); CP_COMMIT();

    float acc[8][4];
#pragma unroll
    for (int nt = 0; nt < 8; nt++)
#pragma unroll
        for (int s = 0; s < 4; s++) acc[nt][s] = 0.f;
    float acc_rs[4] = {0.f, 0.f, 0.f, 0.f};

#pragma unroll 1
    for (int cc = 0; cc < 32; cc++) {
        CP_WAIT1();
        BAR_PAIR(jq + 1);
        if (cc + 2 < 32)
            pf_slice(slice0 + ((cc + 2) % 3) * SLICE_SZ, whsrc, adjsrc, efsrc,
                     jq, cc + 2, lt);
        CP_COMMIT();

        const char*  Sc = sm + (size_t)(jq * 3 + (cc % 3)) * SLICE_SZ;
        const int*   Ac = (const int*)(Sc + ADJ_OFF);
        const float* Ec = (const float*)(Sc + EF_OFF);

#pragma unroll
        for (int kb = 0; kb < 2; kb++) {
            int base0 = lr0 * 36 + kb * 16 + 2 * c;
            int2 x0 = *(const int2*)(Ac + base0);
            int2 x1 = *(const int2*)(Ac + base0 + 8);
            int2 y0 = *(const int2*)(Ac + base0 + 288);       // row +8
            int2 y1 = *(const int2*)(Ac + base0 + 296);
            float4 ef0 = *(const float4*)(Ec + (kb * 16 + 2 * c) * 2);
            float4 ef1 = *(const float4*)(Ec + (kb * 16 + 2 * c + 8) * 2);

            float p00 = x0.x > 0 ? fmaxf(Ei0 * ef0.x, Fi0 * ef0.y) : 0.f;
            float p01 = x0.y > 0 ? fmaxf(Ei0 * ef0.z, Fi0 * ef0.w) : 0.f;
            float p80 = y0.x > 0 ? fmaxf(Ei8 * ef0.x, Fi8 * ef0.y) : 0.f;
            float p81 = y0.y > 0 ? fmaxf(Ei8 * ef0.z, Fi8 * ef0.w) : 0.f;
            float p08 = x1.x > 0 ? fmaxf(Ei0 * ef1.x, Fi0 * ef1.y) : 0.f;
            float p09 = x1.y > 0 ? fmaxf(Ei0 * ef1.z, Fi0 * ef1.w) : 0.f;
            float p88 = y1.x > 0 ? fmaxf(Ei8 * ef1.x, Fi8 * ef1.y) : 0.f;
            float p89 = y1.y > 0 ? fmaxf(Ei8 * ef1.z, Fi8 * ef1.w) : 0.f;

            uint32_t a0 = f16x2(p01, p00);
            uint32_t a1 = f16x2(p81, p80);
            uint32_t a2 = f16x2(p09, p08);
            uint32_t a3 = f16x2(p89, p88);

            const uint2* bq = (const uint2*)(Sc + kb * 2048);
#pragma unroll
            for (int nt = 0; nt < 8; nt++) {
                uint2 bb = bq[(nt * 8 + q) * 4 + c];
                MMA_F16(acc[nt], a0, a1, a2, a3, bb.x, bb.y);
            }
            MMA_F16(acc_rs, a0, a1, a2, a3, ONE_H2, ONE_H2);
        }
    }

    // combine the 2 j-halves via smem (reuses staging)
    float* dsm = (float*)sm;                 // [64][66]
    float* rsm = (float*)(sm + 16896);       // [64]
    __syncthreads();
    if (jq == 1) {
#pragma unroll
        for (int nt = 0; nt < 8; nt++) {
            *(float2*)(dsm + lr0 * 66 + nt * 8 + 2 * c) =
                make_float2(acc[nt][0], acc[nt][1]);
            *(float2*)(dsm + (lr0 + 8) * 66 + nt * 8 + 2 * c) =
                make_float2(acc[nt][2], acc[nt][3]);
        }
        if (c == 0) {
            rsm[lr0]     = acc_rs[0];
            rsm[lr0 + 8] = acc_rs[2];
        }
    }
    __syncthreads();
    if (jq == 0) {
        float i0v = 1.0f / (acc_rs[0] + rsm[lr0]);
        float i8v = 1.0f / (acc_rs[2] + rsm[lr0 + 8]);
        float* o0 = out + (size_t)(rowbase + i0 + lr0) * FOUT;
        float* o8 = out + (size_t)(rowbase + i0 + lr0 + 8) * FOUT;
#pragma unroll
        for (int nt = 0; nt < 8; nt++) {
            int col = nt * 8 + 2 * c;
            float2 d0 = *(const float2*)(dsm + lr0 * 66 + col);
            float2 d8 = *(const float2*)(dsm + (lr0 + 8) * 66 + col);
            float y;
            float2 v0, v8;
            y = (acc[nt][0] + d0.x) * i0v; v0.x = y > 0.f ? y : expm1f(y);
            y = (acc[nt][1] + d0.y) * i0v; v0.y = y > 0.f ? y : expm1f(y);
            y = (acc[nt][2] + d8.x) * i8v; v8.x = y > 0.f ? y : expm1f(y);
            y = (acc[nt][3] + d8.y) * i8v; v8.y = y > 0.f ? y : expm1f(y);
            *(float2*)(o0 + col) = v0;
            *(float2*)(o8 + col) = v8;
        }
    }
}

// ---------------------------------------------------------------------------
extern "C" void kernel_launch(void* const* d_in, const int* in_sizes, int n_in,
                              void* d_out, int out_size) {
    const float* h   = (const float*)d_in[0];
    const int*   adj = (const int*)d_in[1];
    const float* W   = (const float*)d_in[2];
    const float* a   = (const float*)d_in[3];
    float*       out = (float*)d_out;

    const int smemA = HB_OFF + 2 * 9216;   // 83968
    cudaFuncSetAttribute(gat_prep, cudaFuncAttributeMaxDynamicSharedMemorySize, smemA);
    cudaFuncSetAttribute(gat_attn, cudaFuncAttributeMaxDynamicSharedMemorySize, SM_TOTB);

    gat_prep<<<(B_ * N_) / 64, 256, smemA>>>(h, W, a);

    dim3 gridB(N_ / 64, B_);   // (32, 8) = 256 blocks
    gat_attn<<<gridB, 256, SM_TOTB>>>(adj, out);
}

// round 16
// speedup vs baseline: 1.4175x; 1.1985x over previous
#include <cuda_runtime.h>
#include <cstdint>

#define B_     8
#define N_     2048
#define FIN    256
#define FOUT   64
#define LOG2E  1.4426950408889634f
#define ONE_H2 0x3c003c00u   // fp16x2 {1.0, 1.0}

// Scratch (device globals: allocation-free rule)
__device__ uint2  g_WhH[B_ * N_ * FOUT / 4];  // fp16 Wh, quad layout [b][j>>4][o][c]
__device__ float  g_esrc[B_ * N_];            // log2-scaled src logits
__device__ float2 g_edEF[B_ * N_];            // per node: (exp2(d), exp2(0.2 d))

// ---------------------------------------------------------------------------
// helpers
// ---------------------------------------------------------------------------
__device__ __forceinline__ uint32_t smem_u32(const void* p) {
    uint32_t a;
    asm("{ .reg .u64 t; cvta.to.shared.u64 t, %1; cvt.u32.u64 %0, t; }" : "=r"(a) : "l"(p));
    return a;
}
__device__ __forceinline__ void cpa16(uint32_t dst, const void* src) {
    asm volatile("cp.async.cg.shared.global [%0], [%1], 16;" :: "r"(dst), "l"(src));
}
#define CP_COMMIT() asm volatile("cp.async.commit_group;" ::: "memory")
#define CP_WAIT1()  asm volatile("cp.async.wait_group 1;" ::: "memory")
#define BAR_PAIR(id) asm volatile("bar.sync %0, 128;" :: "r"(id) : "memory")

__device__ __forceinline__ float ex2f(float x) {
    float r; asm("ex2.approx.f32 %0, %1;" : "=f"(r) : "f"(x)); return r;
}
__device__ __forceinline__ uint32_t f16x2(float hi, float lo) {
    uint32_t r;
    asm("cvt.rn.satfinite.f16x2.f32 %0, %1, %2;" : "=r"(r) : "f"(hi), "f"(lo));
    return r;
}
// D += A*B, m16n8k16 fp16 -> f32 accum (base PTX ISA)
#define MMA_F16(d, a0, a1, a2, a3, b0, b1)                                    \
    asm volatile("mma.sync.aligned.m16n8k16.row.col.f32.f16.f16.f32 "         \
                 "{%0,%1,%2,%3}, {%4,%5,%6,%7}, {%8,%9}, {%0,%1,%2,%3};"      \
                 : "+f"((d)[0]), "+f"((d)[1]), "+f"((d)[2]), "+f"((d)[3])     \
                 : "r"(a0), "r"(a1), "r"(a2), "r"(a3), "r"(b0), "r"(b1))

// ---------------------------------------------------------------------------
// Kernel PREP v2: Wh = h @ W via fp16 tensor-core MMA (f32 accum).
// 256 blocks x 256 threads, 64 rows/block, 2 blocks/SM (84KB smem).
// Phase 1: build W quads (fp16, [kb][o][c]) + h quads ([kb][row][c]) from
//   cp.async-pipelined fp32 h chunks. Phase 2: 16-kb MMA burst (8 warps:
//   mi=w>>1 rows, nh=w&1 out-half). Phase 3: dump accums -> smem sT, then
//   r15 epilogue: e_src/e_dst dots from accums (e_src error cancels in
//   softmax; e_dst error averages over ~1e3 neighbors), EF, coalesced fp16
//   quad stores.
// ---------------------------------------------------------------------------
#define WQ_OFF  0          // 4096 uint2 = 32KB
#define HQ_OFF  32768      // 4096 uint2 = 32KB
#define H32_OFF 65536      // 2 x 9216 fp32 chunk bufs; reused as sT (16.9KB)
#define SMEM_A  (65536 + 18432)   // 83968

__global__ __launch_bounds__(256, 2) void gat_prep(const float* __restrict__ h,
                                                   const float* __restrict__ W,
                                                   const float* __restrict__ a) {
    extern __shared__ char sA[];
    uint2* wq = (uint2*)(sA + WQ_OFF);
    uint2* hq = (uint2*)(sA + HQ_OFF);
    float* hb = (float*)(sA + H32_OFF);
    uint32_t hbase = smem_u32(sA) + H32_OFF;

    int t = threadIdx.x;
    int row0 = blockIdx.x * 64;

    // h chunk issue: 64 rows x 32 k = 512 x 16B, 2 cp.async per thread
    int r0 = t >> 3, f0 = t & 7;
    int r1 = (t + 256) >> 3;
    const float* hsrc = h + (size_t)row0 * FIN;

    cpa16(hbase + r0 * 144 + f0 * 16, hsrc + (size_t)r0 * FIN + f0 * 4);
    cpa16(hbase + r1 * 144 + f0 * 16, hsrc + (size_t)r1 * FIN + f0 * 4);
    CP_COMMIT();
    cpa16(hbase + 9216 + r0 * 144 + f0 * 16, hsrc + (size_t)r0 * FIN + 32 + f0 * 4);
    cpa16(hbase + 9216 + r1 * 144 + f0 * 16, hsrc + (size_t)r1 * FIN + 32 + f0 * 4);
    CP_COMMIT();

    // build W quads: wq[(kb*64+o)*4+c] = fp16{W[kb16+2c][o],[+1],[+8],[+9]}
#pragma unroll 4
    for (int i = 0; i < 16; i++) {
        int idx = i * 256 + t;
        int kb = idx >> 8, rest = idx & 255;
        int o = rest >> 2, cq = rest & 3;
        int k0 = kb * 16 + 2 * cq;
        float w00 = __ldg(W + (size_t)k0 * FOUT + o);
        float w01 = __ldg(W + (size_t)(k0 + 1) * FOUT + o);
        float w10 = __ldg(W + (size_t)(k0 + 8) * FOUT + o);
        float w11 = __ldg(W + (size_t)(k0 + 9) * FOUT + o);
        uint2 pk;
        pk.x = f16x2(w01, w00);
        pk.y = f16x2(w11, w10);
        wq[idx] = pk;
    }

    // h chunks -> h quads, double-buffered
    for (int c = 0; c < 8; c++) {
        CP_WAIT1();
        __syncthreads();
        const float* hc = hb + (c & 1) * 2304;
#pragma unroll
        for (int i = 0; i < 2; i++) {
            int idx = i * 256 + t;            // 512 quads: (kbl, row, c)
            int kbl = idx >> 8, r2 = idx & 255;
            int row = r2 >> 2, cq = r2 & 3;
            const float* hr = hc + row * 36 + kbl * 16;
            float v0 = hr[2 * cq],     v1 = hr[2 * cq + 1];
            float v2 = hr[2 * cq + 8], v3 = hr[2 * cq + 9];
            uint2 pk;
            pk.x = f16x2(v1, v0);
            pk.y = f16x2(v3, v2);
            hq[((2 * c + kbl) * 64 + row) * 4 + cq] = pk;
        }
        __syncthreads();
        if (c + 2 < 8) {
            uint32_t dst = hbase + (c & 1) * 9216;
            const float* src = hsrc + (c + 2) * 32;
            cpa16(dst + r0 * 144 + f0 * 16, src + (size_t)r0 * FIN + f0 * 4);
            cpa16(dst + r1 * 144 + f0 * 16, src + (size_t)r1 * FIN + f0 * 4);
        }
        CP_COMMIT();
    }
    __syncthreads();

    // MMA burst: warp (mi = w>>1 rows mi*16..+15(+8), nh = w&1 out-half)
    int w = t >> 5, lane = t & 31;
    int q = lane >> 2, cq = lane & 3;
    int mi = w >> 1, nh = w & 1;

    float acc[4][4];
#pragma unroll
    for (int nt = 0; nt < 4; nt++)
#pragma unroll
        for (int s = 0; s < 4; s++) acc[nt][s] = 0.f;

#pragma unroll 4
    for (int kb = 0; kb < 16; kb++) {
        uint2 a02 = hq[((kb * 64) + (mi * 16 + q)) * 4 + cq];
        uint2 a13 = hq[((kb * 64) + (mi * 16 + q + 8)) * 4 + cq];
#pragma unroll
        for (int nt = 0; nt < 4; nt++) {
            uint2 bb = wq[((kb * 64) + (nh * 32 + nt * 8 + q)) * 4 + cq];
            MMA_F16(acc[nt], a02.x, a13.x, a02.y, a13.y, bb.x, bb.y);
        }
    }
    __syncthreads();   // h32 bufs no longer read; reuse as sT

    // dump accums -> sT[row][col] (64 x 66)
    float* sT = (float*)(sA + H32_OFF);
#pragma unroll
    for (int nt = 0; nt < 4; nt++) {
        int col = nh * 32 + nt * 8 + 2 * cq;
        int row = mi * 16 + q;
        *(float2*)(sT + row * 66 + col)       = make_float2(acc[nt][0], acc[nt][1]);
        *(float2*)(sT + (row + 8) * 66 + col) = make_float2(acc[nt][2], acc[nt][3]);
    }
    __syncthreads();

    // r15 epilogue: dots (e_src/e_dst), EF, fp16 quad stores
    int rg = t >> 4, op = t & 15;
    int ov[4] = {2 * op, 2 * op + 1, 2 * op + 32, 2 * op + 33};
    float a1v[4], a2v[4];
#pragma unroll
    for (int s = 0; s < 4; s++) { a1v[s] = a[ov[s]]; a2v[s] = a[FOUT + ov[s]]; }

#pragma unroll
    for (int q2 = 0; q2 < 4; q2++) {
        int r = rg * 4 + q2;
        int grow = row0 + r;
        float v1 = 0.f, v2 = 0.f;
#pragma unroll
        for (int s = 0; s < 4; s++) {
            float v = sT[r * 66 + ov[s]];
            v1 += v * a1v[s];
            v2 += v * a2v[s];
        }
#pragma unroll
        for (int off = 1; off < 16; off <<= 1) {
            v1 += __shfl_xor_sync(0xffffffffu, v1, off);
            v2 += __shfl_xor_sync(0xffffffffu, v2, off);
        }
        if (op == 0) {
            float s = v1 * LOG2E, d = v2 * LOG2E;
            g_esrc[grow] = s;
            g_edEF[grow] = make_float2(ex2f(d), ex2f(0.2f * d));
        }
    }

    // fp16 quad stores: block region = 1024 uint2 contiguous, coalesced
    uint2* gdst = g_WhH + (size_t)blockIdx.x * 1024;
    int o = t >> 2, cs = t & 3;
#pragma unroll
    for (int k = 0; k < 4; k++) {
        int jl = k * 16 + 2 * cs;
        float v00 = sT[jl * 66 + o],       v01 = sT[(jl + 1) * 66 + o];
        float v10 = sT[(jl + 8) * 66 + o], v11 = sT[(jl + 9) * 66 + o];
        uint2 pk;
        pk.x = f16x2(v01, v00);
        pk.y = f16x2(v11, v10);
        gdst[k * 256 + t] = pk;
    }
}

// ---------------------------------------------------------------------------
// Kernel B (r15 verbatim, 36.3us measured): streaming attention,
// mma.sync fp16 m16n8k16 P @ Wh (f32 accum). Grid (32,8), 256 thr, 2 blk/SM.
// 2 PAIRS of 4 warps; slice = fp16 Wh quads 4KB + raw adj 9KB + EF 256B,
// triple-buffered cp.async, pair-scoped named barrier. adj touched once.
// p = adj>0 ? 2^-2 * max(Ei*Ej, Fi*Fj) : 0; rowsum via ones-B MMA.
// ---------------------------------------------------------------------------
#define ADJ_OFF  4096
#define EF_OFF   13312
#define SLICE_SZ 13568                     // 4096 Wh + 9216 adj + 256 EF
#define SM_TOTB  (2 * 3 * SLICE_SZ)        // 81408

__device__ __forceinline__ void pf_slice(uint32_t dst, const char* whsrc,
                                         const char* adjsrc, const float2* efsrc,
                                         int jq, int cc, int lt) {
    const char* wsrc = whsrc + (size_t)(jq * 64 + cc * 2) * 2048;
#pragma unroll
    for (int i = 0; i < 2; i++)
        cpa16(dst + (lt + 128 * i) * 16, wsrc + (size_t)(lt + 128 * i) * 16);
#pragma unroll
    for (int i = 0; i < 4; i++) {
        int idx = i * 128 + lt;
        int r = idx >> 3, u = idx & 7;
        cpa16(dst + ADJ_OFF + r * 144 + u * 16,
              adjsrc + ((size_t)r << 13) + (size_t)(jq * 4096 + cc * 128) + u * 16);
    }
    if (lt < 16)
        cpa16(dst + EF_OFF + lt * 16,
              (const char*)(efsrc + (size_t)jq * 1024 + cc * 32) + lt * 16);
}

__global__ __launch_bounds__(256, 2) void gat_attn(const int* __restrict__ adj,
                                                   float* __restrict__ out) {
    extern __shared__ char sm[];
    uint32_t smb = smem_u32(sm);

    int t = threadIdx.x;
    int w = t >> 5, lane = t & 31;
    int q = lane >> 2, c = lane & 3;
    int b = blockIdx.y;
    int i0 = blockIdx.x * 64;
    int rowbase = b * N_;
    int jq = w >> 2, wp = w & 3;
    int lr0 = wp * 16 + q;
    int lt = t & 127;
    uint32_t slice0 = smb + jq * 3 * SLICE_SZ;

    const char*   whsrc  = (const char*)g_WhH + (size_t)b * (N_ * FOUT * 2);
    const char*   adjsrc = (const char*)(adj + ((size_t)(rowbase + i0) << 11));
    const float2* efsrc  = g_edEF + rowbase;

    float si0 = g_esrc[rowbase + i0 + lr0];
    float si8 = g_esrc[rowbase + i0 + lr0 + 8];
    float Ei0 = ex2f(si0 - 2.0f), Fi0 = ex2f(0.2f * si0 - 2.0f);
    float Ei8 = ex2f(si8 - 2.0f), Fi8 = ex2f(0.2f * si8 - 2.0f);

    pf_slice(slice0, whsrc, adjsrc, efsrc, jq, 0, lt);            CP_COMMIT();
    pf_slice(slice0 + SLICE_SZ, whsrc, adjsrc, efsrc, jq, 1, lt); CP_COMMIT();

    float acc[8][4];
#pragma unroll
    for (int nt = 0; nt < 8; nt++)
#pragma unroll
        for (int s = 0; s < 4; s++) acc[nt][s] = 0.f;
    float acc_rs[4] = {0.f, 0.f, 0.f, 0.f};

#pragma unroll 1
    for (int cc = 0; cc < 32; cc++) {
        CP_WAIT1();
        BAR_PAIR(jq + 1);
        if (cc + 2 < 32)
            pf_slice(slice0 + ((cc + 2) % 3) * SLICE_SZ, whsrc, adjsrc, efsrc,
                     jq, cc + 2, lt);
        CP_COMMIT();

        const char*  Sc = sm + (size_t)(jq * 3 + (cc % 3)) * SLICE_SZ;
        const int*   Ac = (const int*)(Sc + ADJ_OFF);
        const float* Ec = (const float*)(Sc + EF_OFF);

#pragma unroll
        for (int kb = 0; kb < 2; kb++) {
            int base0 = lr0 * 36 + kb * 16 + 2 * c;
            int2 x0 = *(const int2*)(Ac + base0);
            int2 x1 = *(const int2*)(Ac + base0 + 8);
            int2 y0 = *(const int2*)(Ac + base0 + 288);
            int2 y1 = *(const int2*)(Ac + base0 + 296);
            float4 ef0 = *(const float4*)(Ec + (kb * 16 + 2 * c) * 2);
            float4 ef1 = *(const float4*)(Ec + (kb * 16 + 2 * c + 8) * 2);

            float p00 = x0.x > 0 ? fmaxf(Ei0 * ef0.x, Fi0 * ef0.y) : 0.f;
            float p01 = x0.y > 0 ? fmaxf(Ei0 * ef0.z, Fi0 * ef0.w) : 0.f;
            float p80 = y0.x > 0 ? fmaxf(Ei8 * ef0.x, Fi8 * ef0.y) : 0.f;
            float p81 = y0.y > 0 ? fmaxf(Ei8 * ef0.z, Fi8 * ef0.w) : 0.f;
            float p08 = x1.x > 0 ? fmaxf(Ei0 * ef1.x, Fi0 * ef1.y) : 0.f;
            float p09 = x1.y > 0 ? fmaxf(Ei0 * ef1.z, Fi0 * ef1.w) : 0.f;
            float p88 = y1.x > 0 ? fmaxf(Ei8 * ef1.x, Fi8 * ef1.y) : 0.f;
            float p89 = y1.y > 0 ? fmaxf(Ei8 * ef1.z, Fi8 * ef1.w) : 0.f;

            uint32_t a0 = f16x2(p01, p00);
            uint32_t a1 = f16x2(p81, p80);
            uint32_t a2 = f16x2(p09, p08);
            uint32_t a3 = f16x2(p89, p88);

            const uint2* bq = (const uint2*)(Sc + kb * 2048);
#pragma unroll
            for (int nt = 0; nt < 8; nt++) {
                uint2 bb = bq[(nt * 8 + q) * 4 + c];
                MMA_F16(acc[nt], a0, a1, a2, a3, bb.x, bb.y);
            }
            MMA_F16(acc_rs, a0, a1, a2, a3, ONE_H2, ONE_H2);
        }
    }

    // combine the 2 j-halves via smem (reuses staging)
    float* dsm = (float*)sm;                 // [64][66]
    float* rsm = (float*)(sm + 16896);       // [64]
    __syncthreads();
    if (jq == 1) {
#pragma unroll
        for (int nt = 0; nt < 8; nt++) {
            *(float2*)(dsm + lr0 * 66 + nt * 8 + 2 * c) =
                make_float2(acc[nt][0], acc[nt][1]);
            *(float2*)(dsm + (lr0 + 8) * 66 + nt * 8 + 2 * c) =
                make_float2(acc[nt][2], acc[nt][3]);
        }
        if (c == 0) {
            rsm[lr0]     = acc_rs[0];
            rsm[lr0 + 8] = acc_rs[2];
        }
    }
    __syncthreads();
    if (jq == 0) {
        float i0v = 1.0f / (acc_rs[0] + rsm[lr0]);
        float i8v = 1.0f / (acc_rs[2] + rsm[lr0 + 8]);
        float* o0 = out + (size_t)(rowbase + i0 + lr0) * FOUT;
        float* o8 = out + (size_t)(rowbase + i0 + lr0 + 8) * FOUT;
#pragma unroll
        for (int nt = 0; nt < 8; nt++) {
            int col = nt * 8 + 2 * c;
            float2 d0 = *(const float2*)(dsm + lr0 * 66 + col);
            float2 d8 = *(const float2*)(dsm + (lr0 + 8) * 66 + col);
            float y;
            float2 v0, v8;
            y = (acc[nt][0] + d0.x) * i0v; v0.x = y > 0.f ? y : expm1f(y);
            y = (acc[nt][1] + d0.y) * i0v; v0.y = y > 0.f ? y : expm1f(y);
            y = (acc[nt][2] + d8.x) * i8v; v8.x = y > 0.f ? y : expm1f(y);
            y = (acc[nt][3] + d8.y) * i8v; v8.y = y > 0.f ? y : expm1f(y);
            *(float2*)(o0 + col) = v0;
            *(float2*)(o8 + col) = v8;
        }
    }
}

// ---------------------------------------------------------------------------
extern "C" void kernel_launch(void* const* d_in, const int* in_sizes, int n_in,
                              void* d_out, int out_size) {
    const float* h   = (const float*)d_in[0];
    const int*   adj = (const int*)d_in[1];
    const float* W   = (const float*)d_in[2];
    const float* a   = (const float*)d_in[3];
    float*       out = (float*)d_out;

    cudaFuncSetAttribute(gat_prep, cudaFuncAttributeMaxDynamicSharedMemorySize, SMEM_A);
    cudaFuncSetAttribute(gat_attn, cudaFuncAttributeMaxDynamicSharedMemorySize, SM_TOTB);

    gat_prep<<<(B_ * N_) / 64, 256, SMEM_A>>>(h, W, a);

    dim3 gridB(N_ / 64, B_);   // (32, 8) = 256 blocks
    gat_attn<<<gridB, 256, SM_TOTB>>>(adj, out);
}